// round 4
// baseline (speedup 1.0000x reference)
#include <cuda_runtime.h>
#include <cuda_bf16.h>
#include <cstdint>

// Fixed shape: B=2,000,000 rows x F=21 cols, 7 classes (targets[:,2] in
// {100..700}), range penalty on targets[:,1] vs (0, 1000).
constexpr int NF        = 21;
constexpr int BTOT      = 2000000;

constexpr int TILE_ROWS = 128;
constexpr int TILE_EL   = TILE_ROWS * NF;        // 2688 elements
constexpr int TILE_B    = TILE_EL * 4;           // 10752 bytes per array
constexpr int NT        = BTOT / TILE_ROWS;      // 15625 tiles (exact, no tail)
constexpr int NVEC      = TILE_EL / 4;           // 672 float4 per tile

constexpr int STAGES    = 4;
constexpr int BDIM      = 256;
constexpr int WPB       = BDIM / 32;
constexpr int NB        = 296;                   // 148 SMs * 2 CTAs (smem-limited)

// Dynamic smem layout (bytes)
constexpr int OFF_BAR   = 0;                     // 8 mbarriers * 8B: full[4], empty[4]
constexpr int OFF_W     = 128;                   // 7 floats
constexpr int OFF_SA    = 192;                   // float[8]
constexpr int OFF_SP    = 224;                   // float[8]
constexpr int OFF_DA    = 256;                   // double[8]
constexpr int OFF_DP    = 320;                   // double[8]
constexpr int OFF_LAST  = 384;                   // int flag
constexpr int OFF_IN    = 1024;                  // STAGES * 10752
constexpr int OFF_TG    = OFF_IN + STAGES * TILE_B;
constexpr int SMEM_SZ   = OFF_TG + STAGES * TILE_B;   // 87040 B

__device__ double       g_pa[NB];
__device__ double       g_pp[NB];
__device__ unsigned int g_ctr = 0;

__device__ __forceinline__ uint32_t smem_u32(const void* p) {
    uint32_t a;
    asm("{ .reg .u64 t; cvta.to.shared.u64 t, %1; cvt.u32.u64 %0, t; }"
        : "=r"(a) : "l"(p));
    return a;
}
__device__ __forceinline__ void mbar_init(uint32_t a, uint32_t cnt) {
    asm volatile("mbarrier.init.shared.b64 [%0], %1;" :: "r"(a), "r"(cnt) : "memory");
}
__device__ __forceinline__ void mbar_expect_tx(uint32_t a, uint32_t bytes) {
    asm volatile("mbarrier.arrive.expect_tx.shared.b64 _, [%0], %1;"
                 :: "r"(a), "r"(bytes) : "memory");
}
__device__ __forceinline__ void mbar_arrive(uint32_t a) {
    asm volatile("mbarrier.arrive.shared.b64 _, [%0];" :: "r"(a) : "memory");
}
__device__ __forceinline__ void mbar_wait(uint32_t a, uint32_t parity) {
    asm volatile(
        "{\n\t.reg .pred P;\n"
        "W%=:\n\t"
        "mbarrier.try_wait.parity.acquire.cta.shared::cta.b64 P, [%0], %1, 0x989680;\n\t"
        "@P bra D%=;\n\t"
        "bra W%=;\n"
        "D%=:\n\t}"
        :: "r"(a), "r"(parity) : "memory");
}
__device__ __forceinline__ void bulk_g2s(uint32_t dst, const void* src,
                                         uint32_t bytes, uint32_t mbar) {
    asm volatile(
        "cp.async.bulk.shared::cta.global.mbarrier::complete_tx::bytes [%0], [%1], %2, [%3];"
        :: "r"(dst), "l"(src), "r"(bytes), "r"(mbar) : "memory");
}

__global__ void __launch_bounds__(BDIM) wmse_tma(
    const float* __restrict__ in,
    const int*   __restrict__ tg,
    const float* __restrict__ w,
    float*       __restrict__ out)
{
    extern __shared__ char smem[];
    const uint32_t sbase = smem_u32(smem);
    const int tid  = threadIdx.x;
    const int lane = tid & 31;
    const int wid  = tid >> 5;

    float* s_w = reinterpret_cast<float*>(smem + OFF_W);
    if (tid == 0) {
        #pragma unroll
        for (int s = 0; s < STAGES; s++) {
            mbar_init(sbase + OFF_BAR + s * 8,      1u);     // full: tx-based
            mbar_init(sbase + OFF_BAR + 32 + s * 8, BDIM);   // empty: all threads
        }
    }
    if (tid < 7) s_w[tid] = w[tid];
    __syncthreads();

    float acc = 0.0f;   // sum of w[cls_row] * diff^2 (un-normalized)
    float pen = 0.0f;   // range penalty sum

    // Grid-stride over tiles: iteration i -> tile bid + i*NB.
    int i = 0;
    for (int t = blockIdx.x; t < NT; t += NB, i++) {
        const int st = i & (STAGES - 1);
        const uint32_t ph = (uint32_t)((i >> 2) & 1);

        const uint32_t full_b  = sbase + OFF_BAR + st * 8;
        const uint32_t empty_b = sbase + OFF_BAR + 32 + st * 8;
        const uint32_t s_in_a  = sbase + OFF_IN + st * TILE_B;
        const uint32_t s_tg_a  = sbase + OFF_TG + st * TILE_B;

        // ---- producer: one thread refills this stage ----------------------
        if (tid == 0) {
            mbar_wait(empty_b, ph ^ 1u);            // passes immediately first lap
            mbar_expect_tx(full_b, 2u * TILE_B);
            const size_t eoff = (size_t)t * TILE_EL;
            bulk_g2s(s_in_a, in + eoff, TILE_B, full_b);
            bulk_g2s(s_tg_a, tg + eoff, TILE_B, full_b);
        }

        // ---- consumers: wait for data, process from smem -------------------
        mbar_wait(full_b, ph);

        const float* si = reinterpret_cast<const float*>(smem + OFF_IN + st * TILE_B);
        const int*   sg = reinterpret_cast<const int*>(smem + OFF_TG + st * TILE_B);

        // Range penalty: one thread per row (tid < 128).
        if (tid < TILE_ROWS) {
            const float v = (float)sg[tid * NF + 1];
            if (v < 0.0f)         pen = fmaf(v, v, pen);
            else if (v > 1000.0f) { const float u = v - 1000.0f; pen = fmaf(u, u, pen); }
        }

        // Weighted squared-diff: vector-major, weights via direct smem lookup.
        #pragma unroll
        for (int vv = 0; vv < 3; vv++) {
            const int v = tid + vv * BDIM;
            if (v >= NVEC) break;                    // 672 = 2*256 + 160 tail

            const float4 xv = *reinterpret_cast<const float4*>(si + v * 4);
            const int4   tv = *reinterpret_cast<const int4*>(sg + v * 4);

            const unsigned e0  = (unsigned)v * 4u;
            const unsigned r0  = (e0 * 6243u) >> 17;        // e0/21, exact for e0<4228
            const unsigned rem = e0 - r0 * 21u;
            const unsigned r1  = (r0 + 1u < TILE_ROWS) ? r0 + 1u : r0;

            const float d0 = xv.x - (float)tv.x;
            const float d1 = xv.y - (float)tv.y;
            const float d2 = xv.z - (float)tv.z;
            const float d3 = xv.w - (float)tv.w;

            float s0 = 0.0f, s1 = 0.0f;
            if (rem + 0u < 21u) s0 = fmaf(d0, d0, s0); else s1 = fmaf(d0, d0, s1);
            if (rem + 1u < 21u) s0 = fmaf(d1, d1, s0); else s1 = fmaf(d1, d1, s1);
            if (rem + 2u < 21u) s0 = fmaf(d2, d2, s0); else s1 = fmaf(d2, d2, s1);
            if (rem + 3u < 21u) s0 = fmaf(d3, d3, s0); else s1 = fmaf(d3, d3, s1);

            const float w0 = s_w[(unsigned)sg[r0 * NF + 2] / 100u - 1u];
            const float w1 = s_w[(unsigned)sg[r1 * NF + 2] / 100u - 1u];
            acc = fmaf(w0, s0, acc);
            acc = fmaf(w1, s1, acc);
        }

        // ---- release the stage --------------------------------------------
        mbar_arrive(empty_b);
    }

    // ---- warp reduce (fp32), then double across warps ----------------------
    #pragma unroll
    for (int off = 16; off > 0; off >>= 1) {
        acc += __shfl_down_sync(0xFFFFFFFFu, acc, off);
        pen += __shfl_down_sync(0xFFFFFFFFu, pen, off);
    }

    float*  sa = reinterpret_cast<float*>(smem + OFF_SA);
    float*  sp = reinterpret_cast<float*>(smem + OFF_SP);
    int*    s_last = reinterpret_cast<int*>(smem + OFF_LAST);
    if (lane == 0) { sa[wid] = acc; sp[wid] = pen; }
    __syncthreads();

    if (tid == 0) {
        double a = 0.0, p = 0.0;
        #pragma unroll
        for (int k = 0; k < WPB; k++) { a += (double)sa[k]; p += (double)sp[k]; }
        g_pa[blockIdx.x] = a;
        g_pp[blockIdx.x] = p;
        __threadfence();
        const unsigned old = atomicAdd(&g_ctr, 1u);
        *s_last = (old == (unsigned)(NB - 1)) ? 1 : 0;
    }
    __syncthreads();

    // ---- last-arriving block folds all partials ----------------------------
    if (*s_last) {
        double a = 0.0, p = 0.0;
        for (int k = tid; k < NB; k += BDIM) { a += g_pa[k]; p += g_pp[k]; }
        #pragma unroll
        for (int off = 16; off > 0; off >>= 1) {
            a += __shfl_down_sync(0xFFFFFFFFu, a, off);
            p += __shfl_down_sync(0xFFFFFFFFu, p, off);
        }
        double* da = reinterpret_cast<double*>(smem + OFF_DA);
        double* dp = reinterpret_cast<double*>(smem + OFF_DP);
        if (lane == 0) { da[wid] = a; dp[wid] = p; }
        __syncthreads();
        if (tid == 0) {
            double fa = 0.0, fp = 0.0;
            #pragma unroll
            for (int k = 0; k < WPB; k++) { fa += da[k]; fp += dp[k]; }
            out[0] = (float)(fa / ((double)BTOT * (double)NF) + fp);
            g_ctr = 0;   // re-arm for next replay
        }
    }
}

extern "C" void kernel_launch(void* const* d_in, const int* in_sizes, int n_in,
                              void* d_out, int out_size)
{
    const float* in = (const float*)d_in[0];   // inputs  [B, 21] f32
    const int*   tg = (const int*)d_in[1];     // targets [B, 21] i32
    const float* w  = (const float*)d_in[2];   // weights [7]     f32
    float*       out = (float*)d_out;          // scalar  f32

    cudaFuncSetAttribute(wmse_tma, cudaFuncAttributeMaxDynamicSharedMemorySize, SMEM_SZ);
    wmse_tma<<<NB, BDIM, SMEM_SZ>>>(in, tg, w, out);
}

// round 5
// speedup vs baseline: 1.3861x; 1.3861x over previous
#include <cuda_runtime.h>
#include <cuda_bf16.h>

// Fixed shape: B=2,000,000 rows x F=21 cols, 7 classes (targets[:,2] in
// {100..700}), range penalty on targets[:,1] vs (0, 1000).
constexpr int NF    = 21;
constexpr int BTOT  = 2000000;
constexpr int GELEM = 32 * NF;            // 672 floats per 32-row group
constexpr int NVEC  = GELEM / 4;          // 168 float4 per group
constexpr int NGRP  = BTOT / 32;          // 62500 groups

constexpr int BDIM  = 256;
constexpr int WPB   = BDIM / 32;          // 8 warps/block
constexpr int CPSM  = 6;                  // CTAs per SM (reg-capped)
constexpr int NB    = 148 * CPSM;         // 888 blocks
constexpr int TOTW  = NB * WPB;           // 7104 warps grid-wide

__device__ double       g_pa[NB];
__device__ double       g_pp[NB];
__device__ unsigned int g_ctr = 0;        // re-armed by the finishing block

// Process one float4/int4 pair: 4 consecutive elements span at most 2 rows.
// Unweighted squared-diff sums split at the row boundary; 2 shfls apply the
// row weights.
__device__ __forceinline__ void proc_vec(
    float4 xv, int4 tv, unsigned e0, float wl, float& acc)
{
    const unsigned r0  = (e0 * 6243u) >> 17;           // e0/21, exact here
    const unsigned rem = e0 - r0 * 21u;                // 0..20

    const float d0 = xv.x - (float)tv.x;
    const float d1 = xv.y - (float)tv.y;
    const float d2 = xv.z - (float)tv.z;
    const float d3 = xv.w - (float)tv.w;

    float s0 = 0.0f, s1 = 0.0f;
    if (rem + 0u < 21u) s0 = fmaf(d0, d0, s0); else s1 = fmaf(d0, d0, s1);
    if (rem + 1u < 21u) s0 = fmaf(d1, d1, s0); else s1 = fmaf(d1, d1, s1);
    if (rem + 2u < 21u) s0 = fmaf(d2, d2, s0); else s1 = fmaf(d2, d2, s1);
    if (rem + 3u < 21u) s0 = fmaf(d3, d3, s0); else s1 = fmaf(d3, d3, s1);

    const float w0 = __shfl_sync(0xFFFFFFFFu, wl, (int)(r0 & 31u));
    const float w1 = __shfl_sync(0xFFFFFFFFu, wl, (int)((r0 + 1u) & 31u));
    acc = fmaf(w0, s0, acc);
    acc = fmaf(w1, s1, acc);
}

__global__ void __launch_bounds__(BDIM, CPSM) wmse_fused(
    const float* __restrict__ in,
    const int*   __restrict__ tg,
    const float* __restrict__ w,
    float*       __restrict__ out)
{
    const int lane = threadIdx.x & 31;
    const int wid  = threadIdx.x >> 5;
    const int gw   = blockIdx.x * WPB + wid;

    float acc = 0.0f;   // sum of w[cls_row] * diff^2 (un-normalized)
    float pen = 0.0f;   // range penalty sum

    for (int g = gw; g < NGRP; g += TOTW) {
        const size_t base = (size_t)g * GELEM;

        // Per-lane row metadata (same cache lines as the bulk loads).
        const int row = g * 32 + lane;
        const int t1  = __ldg(&tg[(size_t)row * NF + 1]);
        const int t2  = __ldg(&tg[(size_t)row * NF + 2]);
        const float wl = __ldg(&w[t2 / 100 - 1]);     // this lane's row weight

        {
            // Branchless range penalty: v<0 -> v^2, v>1000 -> (v-1000)^2.
            const float v = (float)t1;
            const float u = fmaxf(fmaxf(-v, v - 1000.0f), 0.0f);
            pen = fmaf(u, u, pen);
        }

        const float4* in4 = reinterpret_cast<const float4*>(in + base);
        const int4*   tg4 = reinterpret_cast<const int4*>(tg + base);

        // ---- phase A: vector slots 0,1 ------------------------------------
        {
            float4 x0 = __ldcs(&in4[0 * 32 + lane]);
            float4 x1 = __ldcs(&in4[1 * 32 + lane]);
            int4   t0 = __ldcs(&tg4[0 * 32 + lane]);
            int4   t1v = __ldcs(&tg4[1 * 32 + lane]);
            proc_vec(x0, t0,  (unsigned)(0 * 32 + lane) * 4u, wl, acc);
            proc_vec(x1, t1v, (unsigned)(1 * 32 + lane) * 4u, wl, acc);
        }
        // ---- phase B: vector slots 2,3 ------------------------------------
        {
            float4 x0 = __ldcs(&in4[2 * 32 + lane]);
            float4 x1 = __ldcs(&in4[3 * 32 + lane]);
            int4   t0 = __ldcs(&tg4[2 * 32 + lane]);
            int4   t1v = __ldcs(&tg4[3 * 32 + lane]);
            proc_vec(x0, t0,  (unsigned)(2 * 32 + lane) * 4u, wl, acc);
            proc_vec(x1, t1v, (unsigned)(3 * 32 + lane) * 4u, wl, acc);
        }
        // ---- phase C: vector slot 4 + 8-lane tail slot 5 ------------------
        {
            float4 x0 = __ldcs(&in4[4 * 32 + lane]);
            int4   t0 = __ldcs(&tg4[4 * 32 + lane]);
            float4 x1 = make_float4(0.f, 0.f, 0.f, 0.f);
            int4   t1v = make_int4(0, 0, 0, 0);
            if (lane < NVEC - 160) {                  // lanes 0..7 carry the tail
                x1 = __ldcs(&in4[160 + lane]);
                t1v = __ldcs(&tg4[160 + lane]);
            }
            proc_vec(x0, t0,  (unsigned)(4 * 32 + lane) * 4u, wl, acc);
            proc_vec(x1, t1v, (unsigned)(5 * 32 + lane) * 4u, wl, acc);
        }
    }

    // ---- warp reduce (fp32), then double across warps ----------------------
    #pragma unroll
    for (int off = 16; off > 0; off >>= 1) {
        acc += __shfl_down_sync(0xFFFFFFFFu, acc, off);
        pen += __shfl_down_sync(0xFFFFFFFFu, pen, off);
    }

    __shared__ float sa[WPB], sp[WPB];
    __shared__ bool  s_last;
    if (lane == 0) { sa[wid] = acc; sp[wid] = pen; }
    __syncthreads();

    if (threadIdx.x == 0) {
        double a = 0.0, p = 0.0;
        #pragma unroll
        for (int i = 0; i < WPB; i++) { a += (double)sa[i]; p += (double)sp[i]; }
        g_pa[blockIdx.x] = a;
        g_pp[blockIdx.x] = p;
        __threadfence();
        const unsigned old = atomicAdd(&g_ctr, 1u);
        s_last = (old == (unsigned)(NB - 1));
    }
    __syncthreads();

    // ---- last-arriving block folds all partials (L2-resident) --------------
    if (s_last) {
        double a = 0.0, p = 0.0;
        for (int i = threadIdx.x; i < NB; i += BDIM) { a += g_pa[i]; p += g_pp[i]; }

        #pragma unroll
        for (int off = 16; off > 0; off >>= 1) {
            a += __shfl_down_sync(0xFFFFFFFFu, a, off);
            p += __shfl_down_sync(0xFFFFFFFFu, p, off);
        }
        __shared__ double da[WPB], dp[WPB];
        if (lane == 0) { da[wid] = a; dp[wid] = p; }
        __syncthreads();
        if (threadIdx.x == 0) {
            double fa = 0.0, fp = 0.0;
            #pragma unroll
            for (int i = 0; i < WPB; i++) { fa += da[i]; fp += dp[i]; }
            out[0] = (float)(fa / ((double)BTOT * (double)NF) + fp);
            g_ctr = 0;   // re-arm for the next graph replay
        }
    }
}

extern "C" void kernel_launch(void* const* d_in, const int* in_sizes, int n_in,
                              void* d_out, int out_size)
{
    const float* in = (const float*)d_in[0];   // inputs  [B, 21] f32
    const int*   tg = (const int*)d_in[1];     // targets [B, 21] i32
    const float* w  = (const float*)d_in[2];   // weights [7]     f32
    float*       out = (float*)d_out;          // scalar  f32

    wmse_fused<<<NB, BDIM>>>(in, tg, w, out);
}

// round 6
// speedup vs baseline: 1.6057x; 1.1585x over previous
#include <cuda_runtime.h>
#include <cuda_bf16.h>

// Fixed shape: B=2,000,000 rows x F=21 cols, 7 classes (targets[:,2] in
// {100..700}), range penalty on targets[:,1] vs (0, 1000).
constexpr int NF    = 21;
constexpr int BTOT  = 2000000;
constexpr int GELEM = 32 * NF;            // 672 floats per 32-row group
constexpr int NVEC  = GELEM / 4;          // 168 float4 per group
constexpr int NGRP  = BTOT / 32;          // 62500 groups

constexpr int BDIM  = 256;
constexpr int WPB   = BDIM / 32;          // 8 warps/block
constexpr int NB    = 592;                // 148 SMs * 4 CTAs
constexpr int TOTW  = NB * WPB;           // 4736 warps grid-wide

__device__ double       g_pa[NB];
__device__ double       g_pp[NB];
__device__ unsigned int g_ctr = 0;        // re-armed by the finishing block

// One float4/int4 pair: 4 consecutive elements span at most 2 rows. Split the
// unweighted squared-diff sums at the row boundary; 2 shfls apply row weights.
__device__ __forceinline__ void proc_vec(
    float4 xv, int4 tv, unsigned e0, float wl, float& acc)
{
    const unsigned r0  = (e0 * 6243u) >> 17;           // e0/21, exact here
    const unsigned rem = e0 - r0 * 21u;                // 0..20

    const float d0 = xv.x - (float)tv.x;
    const float d1 = xv.y - (float)tv.y;
    const float d2 = xv.z - (float)tv.z;
    const float d3 = xv.w - (float)tv.w;

    float s0 = 0.0f, s1 = 0.0f;
    if (rem + 0u < 21u) s0 = fmaf(d0, d0, s0); else s1 = fmaf(d0, d0, s1);
    if (rem + 1u < 21u) s0 = fmaf(d1, d1, s0); else s1 = fmaf(d1, d1, s1);
    if (rem + 2u < 21u) s0 = fmaf(d2, d2, s0); else s1 = fmaf(d2, d2, s1);
    if (rem + 3u < 21u) s0 = fmaf(d3, d3, s0); else s1 = fmaf(d3, d3, s1);

    const float w0 = __shfl_sync(0xFFFFFFFFu, wl, (int)(r0 & 31u));
    const float w1 = __shfl_sync(0xFFFFFFFFu, wl, (int)((r0 + 1u) & 31u));
    acc = fmaf(w0, s0, acc);
    acc = fmaf(w1, s1, acc);
}

__global__ void __launch_bounds__(BDIM, 4) wmse_fused(
    const float* __restrict__ in,
    const int*   __restrict__ tg,
    const float* __restrict__ w,
    float*       __restrict__ out)
{
    const int lane = threadIdx.x & 31;
    const int wid  = threadIdx.x >> 5;
    const int gw   = blockIdx.x * WPB + wid;

    // Preload the 7 class weights into lanes 0..6 (one reg per lane).
    float w_reg = 0.0f;
    if (lane < 7) w_reg = __ldg(&w[lane]);

    float acc = 0.0f;   // sum of w[cls_row] * diff^2 (un-normalized)
    float pen = 0.0f;   // range penalty sum

    // Meta prologue for the first iteration: this lane's row metadata.
    int t1c = 0, t2c = 100;
    if (gw < NGRP) {
        const size_t mrow = (size_t)(gw * 32 + lane) * NF;
        t1c = __ldg(&tg[mrow + 1]);
        t2c = __ldg(&tg[mrow + 2]);
    }

    for (int g = gw; g < NGRP; g += TOTW) {
        const size_t base = (size_t)g * GELEM;

        // Resolve this lane's row weight with one shfl (no load chain).
        const int cls = t2c / 100 - 1;                 // {100..700} -> {0..6}
        const float wl = __shfl_sync(0xFFFFFFFFu, w_reg, cls);

        {   // Branchless range penalty on t1.
            const float v = (float)t1c;
            const float u = fmaxf(fmaxf(-v, v - 1000.0f), 0.0f);
            pen = fmaf(u, u, pen);
        }

        const float4* in4 = reinterpret_cast<const float4*>(in + base);
        const int4*   tg4 = reinterpret_cast<const int4*>(tg + base);

        // ---- phase A: vectors 0..2 (6 LDG.128 in flight) -------------------
        float4 xa0 = __ldcs(&in4[0 * 32 + lane]);
        float4 xa1 = __ldcs(&in4[1 * 32 + lane]);
        float4 xa2 = __ldcs(&in4[2 * 32 + lane]);
        int4   ta0 = __ldcs(&tg4[0 * 32 + lane]);
        int4   ta1 = __ldcs(&tg4[1 * 32 + lane]);
        int4   ta2 = __ldcs(&tg4[2 * 32 + lane]);

        proc_vec(xa0, ta0, (unsigned)(0 * 32 + lane) * 4u, wl, acc);
        proc_vec(xa1, ta1, (unsigned)(1 * 32 + lane) * 4u, wl, acc);
        proc_vec(xa2, ta2, (unsigned)(2 * 32 + lane) * 4u, wl, acc);

        // ---- phase B: vectors 3,4 + 8-lane tail vector 5 -------------------
        float4 xb0 = __ldcs(&in4[3 * 32 + lane]);
        float4 xb1 = __ldcs(&in4[4 * 32 + lane]);
        int4   tb0 = __ldcs(&tg4[3 * 32 + lane]);
        int4   tb1 = __ldcs(&tg4[4 * 32 + lane]);

        float4 xb2 = make_float4(0.f, 0.f, 0.f, 0.f);
        int4   tb2 = make_int4(0, 0, 0, 0);
        if (lane < NVEC - 160) {                      // lanes 0..7 carry the tail
            xb2 = __ldcs(&in4[160 + lane]);
            tb2 = __ldcs(&tg4[160 + lane]);
        }

        // ---- prefetch NEXT iteration's meta (overlaps phase-B consume) -----
        {
            const int gn = g + TOTW;
            const size_t mrow = (gn < NGRP)
                ? (size_t)(gn * 32 + lane) * NF
                : (size_t)lane * NF;                  // safe dummy, values unused
            t1c = __ldg(&tg[mrow + 1]);
            t2c = __ldg(&tg[mrow + 2]);
        }

        proc_vec(xb0, tb0, (unsigned)(3 * 32 + lane) * 4u, wl, acc);
        proc_vec(xb1, tb1, (unsigned)(4 * 32 + lane) * 4u, wl, acc);
        proc_vec(xb2, tb2, (unsigned)(5 * 32 + lane) * 4u, wl, acc);
    }

    // ---- warp reduce (fp32), then double across warps ----------------------
    #pragma unroll
    for (int off = 16; off > 0; off >>= 1) {
        acc += __shfl_down_sync(0xFFFFFFFFu, acc, off);
        pen += __shfl_down_sync(0xFFFFFFFFu, pen, off);
    }

    __shared__ float sa[WPB], sp[WPB];
    __shared__ bool  s_last;
    if (lane == 0) { sa[wid] = acc; sp[wid] = pen; }
    __syncthreads();

    if (threadIdx.x == 0) {
        double a = 0.0, p = 0.0;
        #pragma unroll
        for (int i = 0; i < WPB; i++) { a += (double)sa[i]; p += (double)sp[i]; }
        g_pa[blockIdx.x] = a;
        g_pp[blockIdx.x] = p;
        __threadfence();
        const unsigned old = atomicAdd(&g_ctr, 1u);
        s_last = (old == (unsigned)(NB - 1));
    }
    __syncthreads();

    // ---- last-arriving block folds all partials (L2-resident) --------------
    if (s_last) {
        double a = 0.0, p = 0.0;
        for (int i = threadIdx.x; i < NB; i += BDIM) { a += g_pa[i]; p += g_pp[i]; }

        #pragma unroll
        for (int off = 16; off > 0; off >>= 1) {
            a += __shfl_down_sync(0xFFFFFFFFu, a, off);
            p += __shfl_down_sync(0xFFFFFFFFu, p, off);
        }
        __shared__ double da[WPB], dp[WPB];
        if (lane == 0) { da[wid] = a; dp[wid] = p; }
        __syncthreads();
        if (threadIdx.x == 0) {
            double fa = 0.0, fp = 0.0;
            #pragma unroll
            for (int i = 0; i < WPB; i++) { fa += da[i]; fp += dp[i]; }
            out[0] = (float)(fa / ((double)BTOT * (double)NF) + fp);
            g_ctr = 0;   // re-arm for the next graph replay
        }
    }
}

extern "C" void kernel_launch(void* const* d_in, const int* in_sizes, int n_in,
                              void* d_out, int out_size)
{
    const float* in = (const float*)d_in[0];   // inputs  [B, 21] f32
    const int*   tg = (const int*)d_in[1];     // targets [B, 21] i32
    const float* w  = (const float*)d_in[2];   // weights [7]     f32
    float*       out = (float*)d_out;          // scalar  f32

    wmse_fused<<<NB, BDIM>>>(in, tg, w, out);
}